// round 6
// baseline (speedup 1.0000x reference)
#include <cuda_runtime.h>
#include <cuda_bf16.h>
#include <math.h>
#include <stdint.h>

#define NHEADS 16
#define HDIM 128
#define TSEQ 2048
#define BATCH 4
#define HMODEL 2048
#define MROWS (BATCH*TSEQ)   // 8192

// ---------------- scratch (device globals: allocation-free) ----------------
__device__ float g_q[(size_t)BATCH*NHEADS*TSEQ*HDIM];     // [B,nH,T,hd] fp32
__device__ float g_k[(size_t)BATCH*NHEADS*TSEQ*HDIM];
__device__ float g_v[(size_t)BATCH*NHEADS*TSEQ*HDIM];
__device__ float g_ao[(size_t)BATCH*TSEQ*HMODEL];         // [B,T,H]
__device__ float g_cos[TSEQ*64];
__device__ float g_sin[TSEQ*64];
// bf16 hi/lo splits for GEMMs
__device__ __nv_bfloat16 g_xhi[(size_t)MROWS*HMODEL];
__device__ __nv_bfloat16 g_xlo[(size_t)MROWS*HMODEL];
__device__ __nv_bfloat16 g_whi[4][(size_t)HMODEL*HMODEL];   // q,k,v,o
__device__ __nv_bfloat16 g_wlo[4][(size_t)HMODEL*HMODEL];
__device__ __nv_bfloat16 g_aohi[(size_t)MROWS*HMODEL];
__device__ __nv_bfloat16 g_aolo[(size_t)MROWS*HMODEL];
// bf16 hi/lo q,k,v for flash (post-RoPE)
__device__ __nv_bfloat16 g_qhi[(size_t)BATCH*NHEADS*TSEQ*HDIM];
__device__ __nv_bfloat16 g_qlo[(size_t)BATCH*NHEADS*TSEQ*HDIM];
__device__ __nv_bfloat16 g_khi[(size_t)BATCH*NHEADS*TSEQ*HDIM];
__device__ __nv_bfloat16 g_klo[(size_t)BATCH*NHEADS*TSEQ*HDIM];
__device__ __nv_bfloat16 g_vhi[(size_t)BATCH*NHEADS*TSEQ*HDIM];
__device__ __nv_bfloat16 g_vlo[(size_t)BATCH*NHEADS*TSEQ*HDIM];

// ================= PTX helpers (baseline ISA only) ==========================
__device__ __forceinline__ uint32_t smem_u32(const void* p) {
    uint32_t a;
    asm("{ .reg .u64 t; cvta.to.shared.u64 t, %1; cvt.u32.u64 %0, t; }" : "=r"(a) : "l"(p));
    return a;
}
__device__ __forceinline__ void cp16(uint32_t dst, const void* src) {
    asm volatile("cp.async.cg.shared.global [%0], [%1], 16;" :: "r"(dst), "l"(src));
}
#define CP_COMMIT() asm volatile("cp.async.commit_group;" ::: "memory")
#define CP_WAIT(n)  asm volatile("cp.async.wait_group %0;" :: "n"(n) : "memory")

#define LDMX4(r, addr) \
    asm volatile("ldmatrix.sync.aligned.m8n8.x4.shared.b16 {%0,%1,%2,%3}, [%4];" \
        : "=r"((r)[0]), "=r"((r)[1]), "=r"((r)[2]), "=r"((r)[3]) : "r"(addr))
#define LDMX4T(r, addr) \
    asm volatile("ldmatrix.sync.aligned.m8n8.x4.trans.shared.b16 {%0,%1,%2,%3}, [%4];" \
        : "=r"((r)[0]), "=r"((r)[1]), "=r"((r)[2]), "=r"((r)[3]) : "r"(addr))

#define MMA16816(c, a, b) \
    asm volatile("mma.sync.aligned.m16n8k16.row.col.f32.bf16.bf16.f32 " \
        "{%0,%1,%2,%3}, {%4,%5,%6,%7}, {%8,%9}, {%0,%1,%2,%3};" \
        : "+f"((c)[0]), "+f"((c)[1]), "+f"((c)[2]), "+f"((c)[3]) \
        : "r"((a)[0]), "r"((a)[1]), "r"((a)[2]), "r"((a)[3]), "r"((b)[0]), "r"((b)[1]))

// ---------------- fp32 -> bf16 hi/lo split ----------------------------------
__global__ void split_bf16_kernel(const float* __restrict__ src,
                                  __nv_bfloat16* __restrict__ hi,
                                  __nv_bfloat16* __restrict__ lo, int n4) {
    int i = blockIdx.x * blockDim.x + threadIdx.x;
    if (i >= n4) return;
    float4 v = ((const float4*)src)[i];
    float vs[4] = {v.x, v.y, v.z, v.w};
    __nv_bfloat16 h[4], l[4];
    #pragma unroll
    for (int j = 0; j < 4; j++) {
        h[j] = __float2bfloat16(vs[j]);
        l[j] = __float2bfloat16(vs[j] - __bfloat162float(h[j]));
    }
    __nv_bfloat162 h0; h0.x = h[0]; h0.y = h[1];
    __nv_bfloat162 h1; h1.x = h[2]; h1.y = h[3];
    __nv_bfloat162 l0; l0.x = l[0]; l0.y = l[1];
    __nv_bfloat162 l1; l1.x = l[2]; l1.y = l[3];
    ((__nv_bfloat162*)hi)[2*i]   = h0;
    ((__nv_bfloat162*)hi)[2*i+1] = h1;
    ((__nv_bfloat162*)lo)[2*i]   = l0;
    ((__nv_bfloat162*)lo)[2*i+1] = l1;
}

// ---------------- RoPE table -------------------------------------------------
__global__ void rope_table_kernel() {
    int i = blockIdx.x * blockDim.x + threadIdx.x;
    if (i >= TSEQ * 64) return;
    int t = i >> 6, d = i & 63;
    double inv = exp(-((double)(2 * d) / 128.0) * log(10000.0));
    double ang = (double)t * inv;
    double s, c;
    sincos(ang, &s, &c);
    g_cos[i] = (float)c;
    g_sin[i] = (float)s;
}

// -------- RoPE + hi/lo split: q,k (rope) and v (plain split) -----------------
__global__ void rope_split_kernel() {
    int row = blockIdx.x * 8 + threadIdx.y;
    int d   = threadIdx.x;
    int which = blockIdx.y;
    const float* src = (which == 0) ? g_q : (which == 1) ? g_k : g_v;
    __nv_bfloat16* hi = (which == 0) ? g_qhi : (which == 1) ? g_khi : g_vhi;
    __nv_bfloat16* lo = (which == 0) ? g_qlo : (which == 1) ? g_klo : g_vlo;
    size_t base = (size_t)row * HDIM;
    float x0 = src[base + d];
    float x1 = src[base + d + 64];
    float y0, y1;
    if (which < 2) {
        int t = row & (TSEQ - 1);
        float c = g_cos[t * 64 + d], s = g_sin[t * 64 + d];
        y0 = x0 * c - x1 * s;
        y1 = x1 * c + x0 * s;
    } else { y0 = x0; y1 = x1; }
    __nv_bfloat16 h0 = __float2bfloat16(y0);
    __nv_bfloat16 h1 = __float2bfloat16(y1);
    hi[base + d]      = h0;
    hi[base + d + 64] = h1;
    lo[base + d]      = __float2bfloat16(y0 - __bfloat162float(h0));
    lo[base + d + 64] = __float2bfloat16(y1 - __bfloat162float(h1));
}

// ================= warp-mma 3x-bf16 GEMM (occ=2, 2-stage) ====================
#define ROWB 80
#define PART (128 * ROWB)
#define STG  (4 * PART)            // 40960 B per stage
#define NSTG 2

template<int MODE>
__global__ void __launch_bounds__(256, 2)
tc_gemm_kernel(const __nv_bfloat16* __restrict__ Ahi, const __nv_bfloat16* __restrict__ Alo,
               const __nv_bfloat16* __restrict__ Bhi, const __nv_bfloat16* __restrict__ Blo,
               float* __restrict__ C)
{
    extern __shared__ char smem[];
    const uint32_t sb = smem_u32(smem);
    const int tid = threadIdx.x;
    const int lane = tid & 31, w = tid >> 5;
    const int wm = w & 1, wn = w >> 1;

    const __nv_bfloat16* aH = Ahi + (size_t)blockIdx.y * 128 * HMODEL;
    const __nv_bfloat16* aL = Alo + (size_t)blockIdx.y * 128 * HMODEL;
    const __nv_bfloat16* bH = Bhi + (size_t)blockIdx.x * 128 * HMODEL;
    const __nv_bfloat16* bL = Blo + (size_t)blockIdx.x * 128 * HMODEL;

    const int c0 = tid, c1 = tid + 256;
    const int r0 = c0 >> 2, q0 = c0 & 3;
    const int r1 = c1 >> 2, q1 = c1 & 3;

    auto load_stage = [&](int s, int kc) {
        uint32_t base = sb + s * STG;
        size_t g0 = (size_t)r0 * HMODEL + kc * 32 + q0 * 8;
        size_t g1 = (size_t)r1 * HMODEL + kc * 32 + q1 * 8;
        uint32_t d0 = base + r0 * ROWB + q0 * 16;
        uint32_t d1 = base + r1 * ROWB + q1 * 16;
        cp16(d0,            aH + g0);  cp16(d1,            aH + g1);
        cp16(d0 + PART,     aL + g0);  cp16(d1 + PART,     aL + g1);
        cp16(d0 + 2*PART,   bH + g0);  cp16(d1 + 2*PART,   bH + g1);
        cp16(d0 + 3*PART,   bL + g0);  cp16(d1 + 3*PART,   bL + g1);
    };

    float acc[4][4][4];
    #pragma unroll
    for (int i = 0; i < 4; i++)
        #pragma unroll
        for (int j = 0; j < 4; j++)
            #pragma unroll
            for (int e = 0; e < 4; e++) acc[i][j][e] = 0.f;

    load_stage(0, 0); CP_COMMIT();
    load_stage(1, 1); CP_COMMIT();

    const int NKC = HMODEL / 32;   // 64
    for (int kc = 0; kc < NKC; kc++) {
        CP_WAIT(1);
        __syncthreads();
        uint32_t stage = sb + (kc & 1) * STG;

        #pragma unroll
        for (int step = 0; step < 2; step++) {
            // B fragments first (16 regs live)
            uint32_t bhi[4][2], blo[4][2];
            #pragma unroll
            for (int nt2 = 0; nt2 < 2; nt2++) {
                int qd = lane >> 3;
                uint32_t brow = wn * 32 + nt2 * 16 + (qd >> 1) * 8 + (lane & 7);
                uint32_t bd = stage + 2 * PART + brow * ROWB + step * 32 + (qd & 1) * 16;
                uint32_t th[4], tl[4];
                LDMX4(th, bd);
                LDMX4(tl, bd + PART);
                bhi[nt2*2][0] = th[0]; bhi[nt2*2][1] = th[1];
                bhi[nt2*2+1][0] = th[2]; bhi[nt2*2+1][1] = th[3];
                blo[nt2*2][0] = tl[0]; blo[nt2*2][1] = tl[1];
                blo[nt2*2+1][0] = tl[2]; blo[nt2*2+1][1] = tl[3];
            }
            // stream A one m-tile at a time (8 frag regs live)
            #pragma unroll
            for (int mt = 0; mt < 4; mt++) {
                uint32_t ahi[4], alo[4];
                uint32_t arow = wm * 64 + mt * 16 + (lane & 15);
                uint32_t ad = stage + arow * ROWB + step * 32 + (lane >> 4) * 16;
                LDMX4(ahi, ad);
                LDMX4(alo, ad + PART);
                #pragma unroll
                for (int nt = 0; nt < 4; nt++) {
                    MMA16816(acc[mt][nt], ahi, bhi[nt]);
                    MMA16816(acc[mt][nt], ahi, blo[nt]);
                    MMA16816(acc[mt][nt], alo, bhi[nt]);
                }
            }
        }
        __syncthreads();
        if (kc + 2 < NKC) load_stage(kc & 1, kc + 2);
        CP_COMMIT();
    }

    #pragma unroll
    for (int mt = 0; mt < 4; mt++) {
        int mrow = blockIdx.y * 128 + wm * 64 + mt * 16 + (lane >> 2);
        #pragma unroll
        for (int nt = 0; nt < 4; nt++) {
            int n = blockIdx.x * 128 + wn * 32 + nt * 8 + (lane & 3) * 2;
            float* dst;
            if (MODE == 0) {
                dst = C + (size_t)mrow * HMODEL + n;
            } else {
                int b = mrow >> 11, t = mrow & (TSEQ - 1);
                int head = n >> 7, d = n & (HDIM - 1);
                dst = C + (((size_t)(b * NHEADS + head) * TSEQ + t) * HDIM + d);
            }
            float2 v0 = make_float2(acc[mt][nt][0], acc[mt][nt][1]);
            float2 v1 = make_float2(acc[mt][nt][2], acc[mt][nt][3]);
            *(float2*)dst = v0;
            *(float2*)(dst + 8 * (MODE == 0 ? HMODEL : HDIM)) = v1;
        }
    }
}

// ================= mma.sync causal flash attention (unchanged) ===============
#define FROWE 136
#define FROWB (FROWE * 2)
#define FQ_PART (128 * FROWB)
#define FKV_PART (64 * FROWB)
#define FSTAGE (4 * FKV_PART)
#define FQLO_OFF FQ_PART
#define FSTAGE_OFF (2 * FQ_PART)
#define FLASH_SMEM (FSTAGE_OFF + 2 * FSTAGE)   // 208896

__global__ void __launch_bounds__(256, 1) flash_mma_kernel(float* __restrict__ out)
{
    extern __shared__ char fsm[];
    const uint32_t sb = smem_u32(fsm);
    const int qb = blockIdx.x, h = blockIdx.y, b = blockIdx.z;
    const int tid = threadIdx.x, lane = tid & 31, w = tid >> 5;

    const size_t headoff = ((size_t)(b * NHEADS + h) * TSEQ) * HDIM;
    const __nv_bfloat16* qh = g_qhi + headoff + (size_t)qb * 128 * HDIM;
    const __nv_bfloat16* ql = g_qlo + headoff + (size_t)qb * 128 * HDIM;
    const __nv_bfloat16* kh = g_khi + headoff;
    const __nv_bfloat16* kl = g_klo + headoff;
    const __nv_bfloat16* vh = g_vhi + headoff;
    const __nv_bfloat16* vl = g_vlo + headoff;

    #pragma unroll
    for (int t = 0; t < 16; t++) {
        int cid = tid + t * 256;
        int part = cid >> 11;
        int pc = cid & 2047;
        int r = pc >> 4, cq = pc & 15;
        uint32_t dst = sb + part * FQ_PART + r * FROWB + cq * 16;
        const __nv_bfloat16* s = part ? ql : qh;
        cp16(dst, s + (size_t)r * HDIM + cq * 8);
    }

    auto load_kv = [&](int j, int stage) {
        uint32_t base = sb + FSTAGE_OFF + stage * FSTAGE;
        const __nv_bfloat16* srcs[4] = {
            kh + (size_t)j * 64 * HDIM, kl + (size_t)j * 64 * HDIM,
            vh + (size_t)j * 64 * HDIM, vl + (size_t)j * 64 * HDIM };
        #pragma unroll
        for (int t = 0; t < 16; t++) {
            int cid = tid + t * 256;
            int part = cid >> 10;
            int pc = cid & 1023;
            int r = pc >> 4, cq = pc & 15;
            cp16(base + part * FKV_PART + r * FROWB + cq * 16,
                 srcs[part] + (size_t)r * HDIM + cq * 8);
        }
    };

    const int nj = 2 * qb + 2;
    load_kv(0, 0); CP_COMMIT();
    load_kv(1, 1); CP_COMMIT();

    float oacc[16][4];
    #pragma unroll
    for (int i = 0; i < 16; i++)
        #pragma unroll
        for (int e = 0; e < 4; e++) oacc[i][e] = 0.f;
    float m_s[2] = {-1e30f, -1e30f};
    float l_s[2] = {0.f, 0.f};
    const float scale = 0.08838834764831845f;

    for (int j = 0; j < nj; j++) {
        CP_WAIT(1);
        __syncthreads();
        uint32_t stg = sb + FSTAGE_OFF + (j & 1) * FSTAGE;

        float sacc[8][4];
        #pragma unroll
        for (int i = 0; i < 8; i++)
            #pragma unroll
            for (int e = 0; e < 4; e++) sacc[i][e] = 0.f;

        const int qd = lane >> 3;
        #pragma unroll
        for (int kc = 0; kc < 8; kc++) {
            uint32_t ahr[4], alr[4];
            uint32_t arow = w * 16 + (lane & 15);
            uint32_t aad = sb + arow * FROWB + kc * 32 + (lane >> 4) * 16;
            LDMX4(ahr, aad);
            LDMX4(alr, aad + FQLO_OFF);
            #pragma unroll
            for (int nt2 = 0; nt2 < 4; nt2++) {
                uint32_t brow = nt2 * 16 + (qd >> 1) * 8 + (lane & 7);
                uint32_t bad = stg + brow * FROWB + kc * 32 + (qd & 1) * 16;
                uint32_t bh4[4], bl4[4];
                LDMX4(bh4, bad);
                LDMX4(bl4, bad + FKV_PART);
                uint32_t b0h[2] = {bh4[0], bh4[1]}, b1h[2] = {bh4[2], bh4[3]};
                uint32_t b0l[2] = {bl4[0], bl4[1]}, b1l[2] = {bl4[2], bl4[3]};
                MMA16816(sacc[nt2*2],   ahr, b0h);
                MMA16816(sacc[nt2*2],   ahr, b0l);
                MMA16816(sacc[nt2*2],   alr, b0h);
                MMA16816(sacc[nt2*2+1], ahr, b1h);
                MMA16816(sacc[nt2*2+1], ahr, b1l);
                MMA16816(sacc[nt2*2+1], alr, b1h);
            }
        }

        const bool need_mask = (j >= 2 * qb);
        const int rowg0 = qb * 128 + w * 16 + (lane >> 2);
        const int colb = j * 64 + (lane & 3) * 2;
        #pragma unroll
        for (int half = 0; half < 2; half++) {
            int rowg = rowg0 + half * 8;
            float mloc = -1e30f;
            #pragma unroll
            for (int nt = 0; nt < 8; nt++) {
                float v0 = sacc[nt][half*2]     * scale;
                float v1 = sacc[nt][half*2 + 1] * scale;
                if (need_mask) {
                    if (colb + nt * 8     > rowg) v0 = -1e30f;
                    if (colb + nt * 8 + 1 > rowg) v1 = -1e30f;
                }
                sacc[nt][half*2]     = v0;
                sacc[nt][half*2 + 1] = v1;
                mloc = fmaxf(mloc, fmaxf(v0, v1));
            }
            mloc = fmaxf(mloc, __shfl_xor_sync(0xffffffffu, mloc, 1));
            mloc = fmaxf(mloc, __shfl_xor_sync(0xffffffffu, mloc, 2));
            float mn = fmaxf(m_s[half], mloc);
            float corr = __expf(m_s[half] - mn);
            m_s[half] = mn;
            float rsum = 0.f;
            #pragma unroll
            for (int nt = 0; nt < 8; nt++) {
                float p0 = __expf(sacc[nt][half*2]     - mn);
                float p1 = __expf(sacc[nt][half*2 + 1] - mn);
                sacc[nt][half*2]     = p0;
                sacc[nt][half*2 + 1] = p1;
                rsum += p0 + p1;
            }
            rsum += __shfl_xor_sync(0xffffffffu, rsum, 1);
            rsum += __shfl_xor_sync(0xffffffffu, rsum, 2);
            l_s[half] = l_s[half] * corr + rsum;
            #pragma unroll
            for (int nt = 0; nt < 16; nt++) {
                oacc[nt][half*2]     *= corr;
                oacc[nt][half*2 + 1] *= corr;
            }
        }

        #pragma unroll
        for (int kc2 = 0; kc2 < 4; kc2++) {
            uint32_t phi[4], plo[4];
            #pragma unroll
            for (int e = 0; e < 4; e++) {
                int nt = 2 * kc2 + (e >> 1);
                int co = (e & 1) * 2;
                float p0 = sacc[nt][co], p1 = sacc[nt][co + 1];
                uint32_t ph;
                asm("cvt.rn.bf16x2.f32 %0, %1, %2;" : "=r"(ph) : "f"(p1), "f"(p0));
                float h0 = __uint_as_float(ph << 16);
                float h1 = __uint_as_float(ph & 0xffff0000u);
                uint32_t pl;
                asm("cvt.rn.bf16x2.f32 %0, %1, %2;" : "=r"(pl) : "f"(p1 - h1), "f"(p0 - h0));
                phi[e] = ph; plo[e] = pl;
            }
            #pragma unroll
            for (int nt8 = 0; nt8 < 8; nt8++) {
                uint32_t vrow = kc2 * 16 + (qd & 1) * 8 + (lane & 7);
                uint32_t vad = stg + 2 * FKV_PART + vrow * FROWB + nt8 * 32 + (qd >> 1) * 16;
                uint32_t vh4[4], vl4[4];
                LDMX4T(vh4, vad);
                LDMX4T(vl4, vad + FKV_PART);
                uint32_t v0h[2] = {vh4[0], vh4[1]}, v1h[2] = {vh4[2], vh4[3]};
                uint32_t v0l[2] = {vl4[0], vl4[1]}, v1l[2] = {vl4[2], vl4[3]};
                MMA16816(oacc[nt8*2],   phi, v0h);
                MMA16816(oacc[nt8*2],   phi, v0l);
                MMA16816(oacc[nt8*2],   plo, v0h);
                MMA16816(oacc[nt8*2+1], phi, v1h);
                MMA16816(oacc[nt8*2+1], phi, v1l);
                MMA16816(oacc[nt8*2+1], plo, v1h);
            }
        }

        __syncthreads();
        if (j + 2 < nj) load_kv(j + 2, j & 1);
        CP_COMMIT();
    }

    #pragma unroll
    for (int half = 0; half < 2; half++) {
        float inv = 1.0f / l_s[half];
        int t = qb * 128 + w * 16 + (lane >> 2) + half * 8;
        float* dst = out + (((size_t)(b * TSEQ + t) * NHEADS + h) * HDIM);
        #pragma unroll
        for (int nt = 0; nt < 16; nt++) {
            int d = nt * 8 + (lane & 3) * 2;
            float2 val = make_float2(oacc[nt][half*2] * inv, oacc[nt][half*2 + 1] * inv);
            *(float2*)(dst + d) = val;
        }
    }
}

// ---------------- launch -----------------------------------------------------
extern "C" void kernel_launch(void* const* d_in, const int* in_sizes, int n_in,
                              void* d_out, int out_size) {
    const float* x  = (const float*)d_in[0];
    const float* Wq = (const float*)d_in[1];
    const float* Wk = (const float*)d_in[2];
    const float* Wv = (const float*)d_in[3];
    const float* Wo = (const float*)d_in[4];
    float* out = (float*)d_out;

    float *q, *k, *v, *ao;
    cudaGetSymbolAddress((void**)&q,  g_q);
    cudaGetSymbolAddress((void**)&k,  g_k);
    cudaGetSymbolAddress((void**)&v,  g_v);
    cudaGetSymbolAddress((void**)&ao, g_ao);
    __nv_bfloat16 *xhi, *xlo, *whi, *wlo, *aohi, *aolo;
    cudaGetSymbolAddress((void**)&xhi, g_xhi);
    cudaGetSymbolAddress((void**)&xlo, g_xlo);
    cudaGetSymbolAddress((void**)&whi, g_whi);
    cudaGetSymbolAddress((void**)&wlo, g_wlo);
    cudaGetSymbolAddress((void**)&aohi, g_aohi);
    cudaGetSymbolAddress((void**)&aolo, g_aolo);

    const int GEMM_SMEM_BYTES = NSTG * STG;   // 81,920
    cudaFuncSetAttribute(tc_gemm_kernel<0>,
                         cudaFuncAttributeMaxDynamicSharedMemorySize, GEMM_SMEM_BYTES);
    cudaFuncSetAttribute(tc_gemm_kernel<1>,
                         cudaFuncAttributeMaxDynamicSharedMemorySize, GEMM_SMEM_BYTES);
    cudaFuncSetAttribute(flash_mma_kernel,
                         cudaFuncAttributeMaxDynamicSharedMemorySize, FLASH_SMEM);

    rope_table_kernel<<<(TSEQ * 64 + 255) / 256, 256>>>();

    const int NX4 = MROWS * HMODEL / 4;
    const int NW4 = HMODEL * HMODEL / 4;
    const size_t WSTRIDE = (size_t)HMODEL * HMODEL;
    split_bf16_kernel<<<(NX4 + 255) / 256, 256>>>(x, xhi, xlo, NX4);
    split_bf16_kernel<<<(NW4 + 255) / 256, 256>>>(Wq, whi + 0 * WSTRIDE, wlo + 0 * WSTRIDE, NW4);
    split_bf16_kernel<<<(NW4 + 255) / 256, 256>>>(Wk, whi + 1 * WSTRIDE, wlo + 1 * WSTRIDE, NW4);
    split_bf16_kernel<<<(NW4 + 255) / 256, 256>>>(Wv, whi + 2 * WSTRIDE, wlo + 2 * WSTRIDE, NW4);
    split_bf16_kernel<<<(NW4 + 255) / 256, 256>>>(Wo, whi + 3 * WSTRIDE, wlo + 3 * WSTRIDE, NW4);

    dim3 ggrid(HMODEL / 128, MROWS / 128);   // (16, 64)
    tc_gemm_kernel<1><<<ggrid, 256, GEMM_SMEM_BYTES>>>(xhi, xlo, whi + 0 * WSTRIDE, wlo + 0 * WSTRIDE, q);
    tc_gemm_kernel<1><<<ggrid, 256, GEMM_SMEM_BYTES>>>(xhi, xlo, whi + 1 * WSTRIDE, wlo + 1 * WSTRIDE, k);
    tc_gemm_kernel<1><<<ggrid, 256, GEMM_SMEM_BYTES>>>(xhi, xlo, whi + 2 * WSTRIDE, wlo + 2 * WSTRIDE, v);

    rope_split_kernel<<<dim3(BATCH * NHEADS * TSEQ / 8, 3), dim3(64, 8)>>>();

    flash_mma_kernel<<<dim3(TSEQ / 128, NHEADS, BATCH), 256, FLASH_SMEM>>>(ao);

    split_bf16_kernel<<<(NX4 + 255) / 256, 256>>>(ao, aohi, aolo, NX4);
    tc_gemm_kernel<0><<<ggrid, 256, GEMM_SMEM_BYTES>>>(aohi, aolo, whi + 3 * WSTRIDE, wlo + 3 * WSTRIDE, out);
}

// round 7
// speedup vs baseline: 1.5640x; 1.5640x over previous
#include <cuda_runtime.h>
#include <cuda_bf16.h>
#include <math.h>
#include <stdint.h>

#define NHEADS 16
#define HDIM 128
#define TSEQ 2048
#define BATCH 4
#define HMODEL 2048
#define MROWS (BATCH*TSEQ)   // 8192

// ---------------- scratch (device globals: allocation-free) ----------------
__device__ float g_q[(size_t)BATCH*NHEADS*TSEQ*HDIM];     // [B,nH,T,hd] fp32
__device__ float g_k[(size_t)BATCH*NHEADS*TSEQ*HDIM];
__device__ float g_v[(size_t)BATCH*NHEADS*TSEQ*HDIM];
__device__ float g_cos[TSEQ*64];
__device__ float g_sin[TSEQ*64];
// bf16 hi/lo splits for GEMMs
__device__ __nv_bfloat16 g_xhi[(size_t)MROWS*HMODEL];
__device__ __nv_bfloat16 g_xlo[(size_t)MROWS*HMODEL];
__device__ __nv_bfloat16 g_whi[4][(size_t)HMODEL*HMODEL];   // q,k,v,o (contiguous!)
__device__ __nv_bfloat16 g_wlo[4][(size_t)HMODEL*HMODEL];
__device__ __nv_bfloat16 g_aohi[(size_t)MROWS*HMODEL];
__device__ __nv_bfloat16 g_aolo[(size_t)MROWS*HMODEL];
// bf16 hi/lo q,k,v for flash (post-RoPE)
__device__ __nv_bfloat16 g_qhi[(size_t)BATCH*NHEADS*TSEQ*HDIM];
__device__ __nv_bfloat16 g_qlo[(size_t)BATCH*NHEADS*TSEQ*HDIM];
__device__ __nv_bfloat16 g_khi[(size_t)BATCH*NHEADS*TSEQ*HDIM];
__device__ __nv_bfloat16 g_klo[(size_t)BATCH*NHEADS*TSEQ*HDIM];
__device__ __nv_bfloat16 g_vhi[(size_t)BATCH*NHEADS*TSEQ*HDIM];
__device__ __nv_bfloat16 g_vlo[(size_t)BATCH*NHEADS*TSEQ*HDIM];

// ================= PTX helpers (baseline ISA only) ==========================
__device__ __forceinline__ uint32_t smem_u32(const void* p) {
    uint32_t a;
    asm("{ .reg .u64 t; cvta.to.shared.u64 t, %1; cvt.u32.u64 %0, t; }" : "=r"(a) : "l"(p));
    return a;
}
__device__ __forceinline__ void cp16(uint32_t dst, const void* src) {
    asm volatile("cp.async.cg.shared.global [%0], [%1], 16;" :: "r"(dst), "l"(src));
}
#define CP_COMMIT() asm volatile("cp.async.commit_group;" ::: "memory")
#define CP_WAIT(n)  asm volatile("cp.async.wait_group %0;" :: "n"(n) : "memory")

#define LDMX4(r, addr) \
    asm volatile("ldmatrix.sync.aligned.m8n8.x4.shared.b16 {%0,%1,%2,%3}, [%4];" \
        : "=r"((r)[0]), "=r"((r)[1]), "=r"((r)[2]), "=r"((r)[3]) : "r"(addr))
#define LDMX4T(r, addr) \
    asm volatile("ldmatrix.sync.aligned.m8n8.x4.trans.shared.b16 {%0,%1,%2,%3}, [%4];" \
        : "=r"((r)[0]), "=r"((r)[1]), "=r"((r)[2]), "=r"((r)[3]) : "r"(addr))

#define MMA16816(c, a, b) \
    asm volatile("mma.sync.aligned.m16n8k16.row.col.f32.bf16.bf16.f32 " \
        "{%0,%1,%2,%3}, {%4,%5,%6,%7}, {%8,%9}, {%0,%1,%2,%3};" \
        : "+f"((c)[0]), "+f"((c)[1]), "+f"((c)[2]), "+f"((c)[3]) \
        : "r"((a)[0]), "r"((a)[1]), "r"((a)[2]), "r"((a)[3]), "r"((b)[0]), "r"((b)[1]))

// ---------------- fp32 -> bf16 hi/lo split ----------------------------------
__global__ void split_bf16_kernel(const float* __restrict__ src,
                                  __nv_bfloat16* __restrict__ hi,
                                  __nv_bfloat16* __restrict__ lo, int n4) {
    int i = blockIdx.x * blockDim.x + threadIdx.x;
    if (i >= n4) return;
    float4 v = ((const float4*)src)[i];
    float vs[4] = {v.x, v.y, v.z, v.w};
    __nv_bfloat16 h[4], l[4];
    #pragma unroll
    for (int j = 0; j < 4; j++) {
        h[j] = __float2bfloat16(vs[j]);
        l[j] = __float2bfloat16(vs[j] - __bfloat162float(h[j]));
    }
    __nv_bfloat162 h0; h0.x = h[0]; h0.y = h[1];
    __nv_bfloat162 h1; h1.x = h[2]; h1.y = h[3];
    __nv_bfloat162 l0; l0.x = l[0]; l0.y = l[1];
    __nv_bfloat162 l1; l1.x = l[2]; l1.y = l[3];
    ((__nv_bfloat162*)hi)[2*i]   = h0;
    ((__nv_bfloat162*)hi)[2*i+1] = h1;
    ((__nv_bfloat162*)lo)[2*i]   = l0;
    ((__nv_bfloat162*)lo)[2*i+1] = l1;
}

// ---------------- RoPE table -------------------------------------------------
__global__ void rope_table_kernel() {
    int i = blockIdx.x * blockDim.x + threadIdx.x;
    if (i >= TSEQ * 64) return;
    int t = i >> 6, d = i & 63;
    double inv = exp(-((double)(2 * d) / 128.0) * log(10000.0));
    double ang = (double)t * inv;
    double s, c;
    sincos(ang, &s, &c);
    g_cos[i] = (float)c;
    g_sin[i] = (float)s;
}

// -------- RoPE + hi/lo split: q,k (rope) and v (plain split) -----------------
__global__ void rope_split_kernel() {
    int row = blockIdx.x * 8 + threadIdx.y;
    int d   = threadIdx.x;
    int which = blockIdx.y;
    const float* src = (which == 0) ? g_q : (which == 1) ? g_k : g_v;
    __nv_bfloat16* hi = (which == 0) ? g_qhi : (which == 1) ? g_khi : g_vhi;
    __nv_bfloat16* lo = (which == 0) ? g_qlo : (which == 1) ? g_klo : g_vlo;
    size_t base = (size_t)row * HDIM;
    float x0 = src[base + d];
    float x1 = src[base + d + 64];
    float y0, y1;
    if (which < 2) {
        int t = row & (TSEQ - 1);
        float c = g_cos[t * 64 + d], s = g_sin[t * 64 + d];
        y0 = x0 * c - x1 * s;
        y1 = x1 * c + x0 * s;
    } else { y0 = x0; y1 = x1; }
    __nv_bfloat16 h0 = __float2bfloat16(y0);
    __nv_bfloat16 h1 = __float2bfloat16(y1);
    hi[base + d]      = h0;
    hi[base + d + 64] = h1;
    lo[base + d]      = __float2bfloat16(y0 - __bfloat162float(h0));
    lo[base + d + 64] = __float2bfloat16(y1 - __bfloat162float(h1));
}

// ================= warp-mma 3x-bf16 GEMM (occ=2, 2-stage) ====================
// MODE 0: C row-major [M,2048] (final projection).
// MODE 1: fused QKV. B is [6144,2048] (wq,wk,wv concatenated); output scatters
//         to g_q/g_k/g_v in [B,nH,T,hd] depending on n-range.
#define ROWB 80
#define PART (128 * ROWB)
#define STG  (4 * PART)            // 40960 B per stage
#define NSTG 2

template<int MODE>
__global__ void __launch_bounds__(256, 2)
tc_gemm_kernel(const __nv_bfloat16* __restrict__ Ahi, const __nv_bfloat16* __restrict__ Alo,
               const __nv_bfloat16* __restrict__ Bhi, const __nv_bfloat16* __restrict__ Blo,
               float* __restrict__ C0, float* __restrict__ C1, float* __restrict__ C2)
{
    extern __shared__ char smem[];
    const uint32_t sb = smem_u32(smem);
    const int tid = threadIdx.x;
    const int lane = tid & 31, w = tid >> 5;
    const int wm = w & 1, wn = w >> 1;

    const __nv_bfloat16* aH = Ahi + (size_t)blockIdx.y * 128 * HMODEL;
    const __nv_bfloat16* aL = Alo + (size_t)blockIdx.y * 128 * HMODEL;
    const __nv_bfloat16* bH = Bhi + (size_t)blockIdx.x * 128 * HMODEL;
    const __nv_bfloat16* bL = Blo + (size_t)blockIdx.x * 128 * HMODEL;

    const int c0 = tid, c1 = tid + 256;
    const int r0 = c0 >> 2, q0 = c0 & 3;
    const int r1 = c1 >> 2, q1 = c1 & 3;

    auto load_stage = [&](int s, int kc) {
        uint32_t base = sb + s * STG;
        size_t g0 = (size_t)r0 * HMODEL + kc * 32 + q0 * 8;
        size_t g1 = (size_t)r1 * HMODEL + kc * 32 + q1 * 8;
        uint32_t d0 = base + r0 * ROWB + q0 * 16;
        uint32_t d1 = base + r1 * ROWB + q1 * 16;
        cp16(d0,            aH + g0);  cp16(d1,            aH + g1);
        cp16(d0 + PART,     aL + g0);  cp16(d1 + PART,     aL + g1);
        cp16(d0 + 2*PART,   bH + g0);  cp16(d1 + 2*PART,   bH + g1);
        cp16(d0 + 3*PART,   bL + g0);  cp16(d1 + 3*PART,   bL + g1);
    };

    float acc[4][4][4];
    #pragma unroll
    for (int i = 0; i < 4; i++)
        #pragma unroll
        for (int j = 0; j < 4; j++)
            #pragma unroll
            for (int e = 0; e < 4; e++) acc[i][j][e] = 0.f;

    load_stage(0, 0); CP_COMMIT();
    load_stage(1, 1); CP_COMMIT();

    const int NKC = HMODEL / 32;   // 64
    for (int kc = 0; kc < NKC; kc++) {
        CP_WAIT(1);
        __syncthreads();
        uint32_t stage = sb + (kc & 1) * STG;

        #pragma unroll
        for (int step = 0; step < 2; step++) {
            uint32_t bhi[4][2], blo[4][2];
            #pragma unroll
            for (int nt2 = 0; nt2 < 2; nt2++) {
                int qd = lane >> 3;
                uint32_t brow = wn * 32 + nt2 * 16 + (qd >> 1) * 8 + (lane & 7);
                uint32_t bd = stage + 2 * PART + brow * ROWB + step * 32 + (qd & 1) * 16;
                uint32_t th[4], tl[4];
                LDMX4(th, bd);
                LDMX4(tl, bd + PART);
                bhi[nt2*2][0] = th[0]; bhi[nt2*2][1] = th[1];
                bhi[nt2*2+1][0] = th[2]; bhi[nt2*2+1][1] = th[3];
                blo[nt2*2][0] = tl[0]; blo[nt2*2][1] = tl[1];
                blo[nt2*2+1][0] = tl[2]; blo[nt2*2+1][1] = tl[3];
            }
            #pragma unroll
            for (int mt = 0; mt < 4; mt++) {
                uint32_t ahi[4], alo[4];
                uint32_t arow = wm * 64 + mt * 16 + (lane & 15);
                uint32_t ad = stage + arow * ROWB + step * 32 + (lane >> 4) * 16;
                LDMX4(ahi, ad);
                LDMX4(alo, ad + PART);
                #pragma unroll
                for (int nt = 0; nt < 4; nt++) {
                    MMA16816(acc[mt][nt], ahi, bhi[nt]);
                    MMA16816(acc[mt][nt], ahi, blo[nt]);
                    MMA16816(acc[mt][nt], alo, bhi[nt]);
                }
            }
        }
        __syncthreads();
        if (kc + 2 < NKC) load_stage(kc & 1, kc + 2);
        CP_COMMIT();
    }

    // epilogue
    float* dstbase;
    int which = 0;
    if (MODE == 1) {
        int nglob = blockIdx.x * 128;
        which = nglob >> 11;               // 0:q 1:k 2:v
    }
    dstbase = (MODE == 0) ? C0 : (which == 0 ? C0 : (which == 1 ? C1 : C2));

    #pragma unroll
    for (int mt = 0; mt < 4; mt++) {
        int mrow = blockIdx.y * 128 + wm * 64 + mt * 16 + (lane >> 2);
        #pragma unroll
        for (int nt = 0; nt < 4; nt++) {
            int n = blockIdx.x * 128 + wn * 32 + nt * 8 + (lane & 3) * 2;
            float* dst;
            if (MODE == 0) {
                dst = dstbase + (size_t)mrow * HMODEL + n;
            } else {
                int nin = n & 2047;
                int b = mrow >> 11, t = mrow & (TSEQ - 1);
                int head = nin >> 7, d = nin & (HDIM - 1);
                dst = dstbase + (((size_t)(b * NHEADS + head) * TSEQ + t) * HDIM + d);
            }
            float2 v0 = make_float2(acc[mt][nt][0], acc[mt][nt][1]);
            float2 v1 = make_float2(acc[mt][nt][2], acc[mt][nt][3]);
            *(float2*)dst = v0;
            *(float2*)(dst + 8 * (MODE == 0 ? HMODEL : HDIM)) = v1;
        }
    }
}

// ================= mma.sync causal flash attention ===========================
// Epilogue now writes bf16 hi/lo (aohi/aolo) directly — no fp32 ao round trip.
#define FROWE 136
#define FROWB (FROWE * 2)
#define FQ_PART (128 * FROWB)
#define FKV_PART (64 * FROWB)
#define FSTAGE (4 * FKV_PART)
#define FQLO_OFF FQ_PART
#define FSTAGE_OFF (2 * FQ_PART)
#define FLASH_SMEM (FSTAGE_OFF + 2 * FSTAGE)   // 208896

__global__ void __launch_bounds__(256, 1) flash_mma_kernel(
    __nv_bfloat16* __restrict__ outhi, __nv_bfloat16* __restrict__ outlo)
{
    extern __shared__ char fsm[];
    const uint32_t sb = smem_u32(fsm);
    const int qb = blockIdx.x, h = blockIdx.y, b = blockIdx.z;
    const int tid = threadIdx.x, lane = tid & 31, w = tid >> 5;

    const size_t headoff = ((size_t)(b * NHEADS + h) * TSEQ) * HDIM;
    const __nv_bfloat16* qh = g_qhi + headoff + (size_t)qb * 128 * HDIM;
    const __nv_bfloat16* ql = g_qlo + headoff + (size_t)qb * 128 * HDIM;
    const __nv_bfloat16* kh = g_khi + headoff;
    const __nv_bfloat16* kl = g_klo + headoff;
    const __nv_bfloat16* vh = g_vhi + headoff;
    const __nv_bfloat16* vl = g_vlo + headoff;

    #pragma unroll
    for (int t = 0; t < 16; t++) {
        int cid = tid + t * 256;
        int part = cid >> 11;
        int pc = cid & 2047;
        int r = pc >> 4, cq = pc & 15;
        uint32_t dst = sb + part * FQ_PART + r * FROWB + cq * 16;
        const __nv_bfloat16* s = part ? ql : qh;
        cp16(dst, s + (size_t)r * HDIM + cq * 8);
    }

    auto load_kv = [&](int j, int stage) {
        uint32_t base = sb + FSTAGE_OFF + stage * FSTAGE;
        const __nv_bfloat16* srcs[4] = {
            kh + (size_t)j * 64 * HDIM, kl + (size_t)j * 64 * HDIM,
            vh + (size_t)j * 64 * HDIM, vl + (size_t)j * 64 * HDIM };
        #pragma unroll
        for (int t = 0; t < 16; t++) {
            int cid = tid + t * 256;
            int part = cid >> 10;
            int pc = cid & 1023;
            int r = pc >> 4, cq = pc & 15;
            cp16(base + part * FKV_PART + r * FROWB + cq * 16,
                 srcs[part] + (size_t)r * HDIM + cq * 8);
        }
    };

    const int nj = 2 * qb + 2;
    load_kv(0, 0); CP_COMMIT();
    load_kv(1, 1); CP_COMMIT();

    float oacc[16][4];
    #pragma unroll
    for (int i = 0; i < 16; i++)
        #pragma unroll
        for (int e = 0; e < 4; e++) oacc[i][e] = 0.f;
    float m_s[2] = {-1e30f, -1e30f};
    float l_s[2] = {0.f, 0.f};
    const float scale = 0.08838834764831845f;

    for (int j = 0; j < nj; j++) {
        CP_WAIT(1);
        __syncthreads();
        uint32_t stg = sb + FSTAGE_OFF + (j & 1) * FSTAGE;

        float sacc[8][4];
        #pragma unroll
        for (int i = 0; i < 8; i++)
            #pragma unroll
            for (int e = 0; e < 4; e++) sacc[i][e] = 0.f;

        const int qd = lane >> 3;
        #pragma unroll
        for (int kc = 0; kc < 8; kc++) {
            uint32_t ahr[4], alr[4];
            uint32_t arow = w * 16 + (lane & 15);
            uint32_t aad = sb + arow * FROWB + kc * 32 + (lane >> 4) * 16;
            LDMX4(ahr, aad);
            LDMX4(alr, aad + FQLO_OFF);
            #pragma unroll
            for (int nt2 = 0; nt2 < 4; nt2++) {
                uint32_t brow = nt2 * 16 + (qd >> 1) * 8 + (lane & 7);
                uint32_t bad = stg + brow * FROWB + kc * 32 + (qd & 1) * 16;
                uint32_t bh4[4], bl4[4];
                LDMX4(bh4, bad);
                LDMX4(bl4, bad + FKV_PART);
                uint32_t b0h[2] = {bh4[0], bh4[1]}, b1h[2] = {bh4[2], bh4[3]};
                uint32_t b0l[2] = {bl4[0], bl4[1]}, b1l[2] = {bl4[2], bl4[3]};
                MMA16816(sacc[nt2*2],   ahr, b0h);
                MMA16816(sacc[nt2*2],   ahr, b0l);
                MMA16816(sacc[nt2*2],   alr, b0h);
                MMA16816(sacc[nt2*2+1], ahr, b1h);
                MMA16816(sacc[nt2*2+1], ahr, b1l);
                MMA16816(sacc[nt2*2+1], alr, b1h);
            }
        }

        const bool need_mask = (j >= 2 * qb);
        const int rowg0 = qb * 128 + w * 16 + (lane >> 2);
        const int colb = j * 64 + (lane & 3) * 2;
        #pragma unroll
        for (int half = 0; half < 2; half++) {
            int rowg = rowg0 + half * 8;
            float mloc = -1e30f;
            #pragma unroll
            for (int nt = 0; nt < 8; nt++) {
                float v0 = sacc[nt][half*2]     * scale;
                float v1 = sacc[nt][half*2 + 1] * scale;
                if (need_mask) {
                    if (colb + nt * 8     > rowg) v0 = -1e30f;
                    if (colb + nt * 8 + 1 > rowg) v1 = -1e30f;
                }
                sacc[nt][half*2]     = v0;
                sacc[nt][half*2 + 1] = v1;
                mloc = fmaxf(mloc, fmaxf(v0, v1));
            }
            mloc = fmaxf(mloc, __shfl_xor_sync(0xffffffffu, mloc, 1));
            mloc = fmaxf(mloc, __shfl_xor_sync(0xffffffffu, mloc, 2));
            float mn = fmaxf(m_s[half], mloc);
            float corr = __expf(m_s[half] - mn);
            m_s[half] = mn;
            float rsum = 0.f;
            #pragma unroll
            for (int nt = 0; nt < 8; nt++) {
                float p0 = __expf(sacc[nt][half*2]     - mn);
                float p1 = __expf(sacc[nt][half*2 + 1] - mn);
                sacc[nt][half*2]     = p0;
                sacc[nt][half*2 + 1] = p1;
                rsum += p0 + p1;
            }
            rsum += __shfl_xor_sync(0xffffffffu, rsum, 1);
            rsum += __shfl_xor_sync(0xffffffffu, rsum, 2);
            l_s[half] = l_s[half] * corr + rsum;
            #pragma unroll
            for (int nt = 0; nt < 16; nt++) {
                oacc[nt][half*2]     *= corr;
                oacc[nt][half*2 + 1] *= corr;
            }
        }

        #pragma unroll
        for (int kc2 = 0; kc2 < 4; kc2++) {
            uint32_t phi[4], plo[4];
            #pragma unroll
            for (int e = 0; e < 4; e++) {
                int nt = 2 * kc2 + (e >> 1);
                int co = (e & 1) * 2;
                float p0 = sacc[nt][co], p1 = sacc[nt][co + 1];
                uint32_t ph;
                asm("cvt.rn.bf16x2.f32 %0, %1, %2;" : "=r"(ph) : "f"(p1), "f"(p0));
                float h0 = __uint_as_float(ph << 16);
                float h1 = __uint_as_float(ph & 0xffff0000u);
                uint32_t pl;
                asm("cvt.rn.bf16x2.f32 %0, %1, %2;" : "=r"(pl) : "f"(p1 - h1), "f"(p0 - h0));
                phi[e] = ph; plo[e] = pl;
            }
            #pragma unroll
            for (int nt8 = 0; nt8 < 8; nt8++) {
                uint32_t vrow = kc2 * 16 + (qd & 1) * 8 + (lane & 7);
                uint32_t vad = stg + 2 * FKV_PART + vrow * FROWB + nt8 * 32 + (qd >> 1) * 16;
                uint32_t vh4[4], vl4[4];
                LDMX4T(vh4, vad);
                LDMX4T(vl4, vad + FKV_PART);
                uint32_t v0h[2] = {vh4[0], vh4[1]}, v1h[2] = {vh4[2], vh4[3]};
                uint32_t v0l[2] = {vl4[0], vl4[1]}, v1l[2] = {vl4[2], vl4[3]};
                MMA16816(oacc[nt8*2],   phi, v0h);
                MMA16816(oacc[nt8*2],   phi, v0l);
                MMA16816(oacc[nt8*2],   plo, v0h);
                MMA16816(oacc[nt8*2+1], phi, v1h);
                MMA16816(oacc[nt8*2+1], phi, v1l);
                MMA16816(oacc[nt8*2+1], plo, v1h);
            }
        }

        __syncthreads();
        if (j + 2 < nj) load_kv(j + 2, j & 1);
        CP_COMMIT();
    }

    // ---- epilogue: normalize, write bf16 hi/lo [B,T,H] ----
    #pragma unroll
    for (int half = 0; half < 2; half++) {
        float inv = 1.0f / l_s[half];
        int t = qb * 128 + w * 16 + (lane >> 2) + half * 8;
        size_t rowoff = (((size_t)(b * TSEQ + t) * NHEADS + h) * HDIM);
        #pragma unroll
        for (int nt = 0; nt < 16; nt++) {
            int d = nt * 8 + (lane & 3) * 2;
            float y0 = oacc[nt][half*2] * inv;
            float y1 = oacc[nt][half*2 + 1] * inv;
            __nv_bfloat16 h0 = __float2bfloat16(y0);
            __nv_bfloat16 h1 = __float2bfloat16(y1);
            __nv_bfloat162 hv; hv.x = h0; hv.y = h1;
            __nv_bfloat162 lv;
            lv.x = __float2bfloat16(y0 - __bfloat162float(h0));
            lv.y = __float2bfloat16(y1 - __bfloat162float(h1));
            *(__nv_bfloat162*)(outhi + rowoff + d) = hv;
            *(__nv_bfloat162*)(outlo + rowoff + d) = lv;
        }
    }
}

// ---------------- launch -----------------------------------------------------
extern "C" void kernel_launch(void* const* d_in, const int* in_sizes, int n_in,
                              void* d_out, int out_size) {
    const float* x  = (const float*)d_in[0];
    const float* Wq = (const float*)d_in[1];
    const float* Wk = (const float*)d_in[2];
    const float* Wv = (const float*)d_in[3];
    const float* Wo = (const float*)d_in[4];
    float* out = (float*)d_out;

    float *q, *k, *v;
    cudaGetSymbolAddress((void**)&q,  g_q);
    cudaGetSymbolAddress((void**)&k,  g_k);
    cudaGetSymbolAddress((void**)&v,  g_v);
    __nv_bfloat16 *xhi, *xlo, *whi, *wlo, *aohi, *aolo;
    cudaGetSymbolAddress((void**)&xhi, g_xhi);
    cudaGetSymbolAddress((void**)&xlo, g_xlo);
    cudaGetSymbolAddress((void**)&whi, g_whi);
    cudaGetSymbolAddress((void**)&wlo, g_wlo);
    cudaGetSymbolAddress((void**)&aohi, g_aohi);
    cudaGetSymbolAddress((void**)&aolo, g_aolo);

    const int GEMM_SMEM_BYTES = NSTG * STG;   // 81,920
    cudaFuncSetAttribute(tc_gemm_kernel<0>,
                         cudaFuncAttributeMaxDynamicSharedMemorySize, GEMM_SMEM_BYTES);
    cudaFuncSetAttribute(tc_gemm_kernel<1>,
                         cudaFuncAttributeMaxDynamicSharedMemorySize, GEMM_SMEM_BYTES);
    cudaFuncSetAttribute(flash_mma_kernel,
                         cudaFuncAttributeMaxDynamicSharedMemorySize, FLASH_SMEM);

    rope_table_kernel<<<(TSEQ * 64 + 255) / 256, 256>>>();

    const int NX4 = MROWS * HMODEL / 4;
    const int NW4 = HMODEL * HMODEL / 4;
    const size_t WSTRIDE = (size_t)HMODEL * HMODEL;
    split_bf16_kernel<<<(NX4 + 255) / 256, 256>>>(x, xhi, xlo, NX4);
    split_bf16_kernel<<<(NW4 + 255) / 256, 256>>>(Wq, whi + 0 * WSTRIDE, wlo + 0 * WSTRIDE, NW4);
    split_bf16_kernel<<<(NW4 + 255) / 256, 256>>>(Wk, whi + 1 * WSTRIDE, wlo + 1 * WSTRIDE, NW4);
    split_bf16_kernel<<<(NW4 + 255) / 256, 256>>>(Wv, whi + 2 * WSTRIDE, wlo + 2 * WSTRIDE, NW4);
    split_bf16_kernel<<<(NW4 + 255) / 256, 256>>>(Wo, whi + 3 * WSTRIDE, wlo + 3 * WSTRIDE, NW4);

    // ONE fused QKV GEMM: B = [6144, 2048] (wq|wk|wv hi/lo are contiguous)
    dim3 qkvgrid(3 * HMODEL / 128, MROWS / 128);   // (48, 64)
    tc_gemm_kernel<1><<<qkvgrid, 256, GEMM_SMEM_BYTES>>>(xhi, xlo, whi, wlo, q, k, v);

    rope_split_kernel<<<dim3(BATCH * NHEADS * TSEQ / 8, 3), dim3(64, 8)>>>();

    flash_mma_kernel<<<dim3(TSEQ / 128, NHEADS, BATCH), 256, FLASH_SMEM>>>(aohi, aolo);

    dim3 ogrid(HMODEL / 128, MROWS / 128);   // (16, 64)
    tc_gemm_kernel<0><<<ogrid, 256, GEMM_SMEM_BYTES>>>(aohi, aolo, whi + 3 * WSTRIDE, wlo + 3 * WSTRIDE, out, nullptr, nullptr);
}